// round 1
// baseline (speedup 1.0000x reference)
#include <cuda_runtime.h>
#include <cuda_bf16.h>

#define NSTEP 730
#define NG    2000
#define MU    16
#define NOUT  500
#define PRECS 1e-5f

// Scratch: qA[t][g] = mean_mu(Q0+Q1+Q2) * Ai[g]
__device__ float g_qA[NSTEP * NG];

// ---------------------------------------------------------------------------
// Kernel 1: the HBV scan. One thread per (grid, mu) lane. 32,000 threads.
// ---------------------------------------------------------------------------
__global__ __launch_bounds__(128)
void hbv_scan_kernel(const float* __restrict__ x,          // (730, 2000, 3)
                     const float* __restrict__ params,     // (730, 2000, 3, 16)
                     const float* __restrict__ wl,         // (2000, 13, 16)
                     const float* __restrict__ Ai,         // (2000,)
                     const float* __restrict__ Acb)        // (2000,)
{
    int tid = blockIdx.x * blockDim.x + threadIdx.x;
    if (tid >= NG * MU) return;
    int g = tid >> 4;
    int m = tid & 15;

    // ---- per-(g,m) waterloss parameters, scaled by SCA2 ----
    const float* w = wl + (size_t)g * 13 * MU + m;
    float parFC    = 50.0f   + w[0  * MU] * (1000.0f - 50.0f);
    float parK1    = 0.01f   + w[1  * MU] * (0.5f   - 0.01f);
    float parK2    = 0.001f  + w[2  * MU] * (0.2f   - 0.001f);
    float parLP    = 0.2f    + w[3  * MU] * (1.0f   - 0.2f);
    float parPERC  =           w[4  * MU] * 10.0f;
    float parUZL   =           w[5  * MU] * 100.0f;
    float parTT    = -2.5f   + w[6  * MU] * 5.0f;
    float parCFMAX = 0.5f    + w[7  * MU] * (10.0f  - 0.5f);
    float parCFR   =           w[8  * MU] * 0.1f;
    float parCWH   =           w[9  * MU] * 0.2f;
    float parC     =           w[10 * MU] * 1.0f;
    float parTR    =           w[11 * MU] * 20.0f;
    float parAc    =           w[12 * MU] * 2500.0f;

    float Ac  = Acb[g];
    float Aig = Ai[g];

    // regional_flow (computed once)
    float rf;
    {
        float c1 = fminf(fmaxf((Ac - parAc) * (1.0f / 1000.0f), -1.0f), 1.0f);
        float ea = fminf(fmaxf(-(Ac - 2500.0f) * (1.0f / 50.0f), -10.0f), 0.0f);
        float e  = expf(ea);
        rf = (Ac < 2500.0f) ? (c1 * parTR) : (e * parTR);
    }

    float invFC   = 1.0f / parFC;
    float invLPFC = 1.0f / (parLP * parFC);
    float CFRCF   = parCFR * parCFMAX;

    float SNOWPACK = 0.001f, MELTWATER = 0.001f, SM = 0.001f, SUZ = 0.001f, SLZ = 0.001f;

    const float* pp = params + (size_t)g * 3 * MU + m;   // stride per t: NG*3*MU
    const float* xp = x + (size_t)g * 3;                 // stride per t: NG*3

    // prime the pipeline (t = 0 loads)
    float rb  = pp[0];
    float rk  = pp[MU];
    float rbe = pp[2 * MU];
    float Pt  = xp[0];
    float Tt  = xp[1];
    float Et  = xp[2];

    float* qrow = g_qA + g;

    for (int t = 0; t < NSTEP; t++) {
        // ---- prefetch t+1 while computing t ----
        float nrb = 0.f, nrk = 0.f, nrbe = 0.f, nP = 0.f, nT = 0.f, nE = 0.f;
        if (t + 1 < NSTEP) {
            pp += NG * 3 * MU;
            xp += NG * 3;
            nrb  = pp[0];
            nrk  = pp[MU];
            nrbe = pp[2 * MU];
            nP   = xp[0];
            nT   = xp[1];
            nE   = xp[2];
        }

        // ---- scale time-varying parameters (SCA1) ----
        float parBETA   = 1.0f  + rb  * 5.0f;
        float parK0     = 0.05f + rk  * 0.85f;
        float parBETAET = 0.3f  + rbe * 4.7f;

        // ---- HBV step ----
        float RAIN = (Tt >= parTT) ? Pt : 0.0f;
        float SNOW = Pt - RAIN;
        SNOWPACK += SNOW;
        float melt = fminf(fmaxf(parCFMAX * (Tt - parTT), 0.0f), SNOWPACK);
        MELTWATER += melt;
        SNOWPACK  -= melt;
        float refr = fminf(fmaxf(CFRCF * (parTT - Tt), 0.0f), MELTWATER);
        SNOWPACK  += refr;
        MELTWATER -= refr;
        float tosoil = fmaxf(MELTWATER - parCWH * SNOWPACK, 0.0f);
        MELTWATER -= tosoil;

        float sw = fminf(fmaxf(__powf(SM * invFC, parBETA), 0.0f), 1.0f);
        float recharge = (RAIN + tosoil) * sw;
        SM += RAIN + tosoil - recharge;
        float excess = fmaxf(SM - parFC, 0.0f);
        SM -= excess;

        float ef = fminf(fmaxf(__powf(SM * invLPFC, parBETAET), 0.0f), 1.0f);
        float ETact = fminf(SM, Et * ef);
        SM = fmaxf(SM - ETact, PRECS);

        float cap = fminf(SLZ, parC * SLZ * (1.0f - fminf(SM * invFC, 1.0f)));
        SM  = fmaxf(SM + cap, PRECS);
        SLZ = fmaxf(SLZ - cap, PRECS);

        SUZ += recharge + excess;
        float PERC = fminf(SUZ, parPERC);
        SUZ -= PERC;
        float Q0 = parK0 * fmaxf(SUZ - parUZL, 0.0f);
        SUZ -= Q0;
        float Q1 = parK1 * SUZ;
        SUZ -= Q1;
        SLZ += PERC;
        SLZ  = fmaxf(SLZ + rf, 0.0f);
        float Q2 = parK2 * SLZ;
        SLZ -= Q2;

        float q = Q0 + Q1 + Q2;
        // mean over the 16 mu-lanes (lanes m..m^15 live in one half-warp group)
        q += __shfl_xor_sync(0xffffffffu, q, 8);
        q += __shfl_xor_sync(0xffffffffu, q, 4);
        q += __shfl_xor_sync(0xffffffffu, q, 2);
        q += __shfl_xor_sync(0xffffffffu, q, 1);
        if (m == 0) qrow[(size_t)t * NG] = q * 0.0625f * Aig;

        rb = nrb; rk = nrk; rbe = nrbe;
        Pt = nP;  Tt = nT;  Et = nE;
    }
}

// ---------------------------------------------------------------------------
// Kernel 2: out[t][o] = sum_g qA[t][g] * idx[g][o]
// SGEMM M=730 (t), N=500 (o), K=2000 (g). 32x32 tile, 4x4 per thread, BK=40.
// ---------------------------------------------------------------------------
#define BM 32
#define BN 32
#define BK 40

__global__ __launch_bounds__(64)
void agg_gemm_kernel(const float* __restrict__ idxm,  // (2000, 500)
                     float* __restrict__ out)         // (730, 500)
{
    __shared__ float sA[BK][BM + 1];  // sA[k][m] : qA tile (padded, conflict-free)
    __shared__ float sB[BK][BN];      // sB[k][n] : idx tile

    int bm = blockIdx.y * BM;
    int bn = blockIdx.x * BN;
    int tx = threadIdx.x & 7;   // 0..7  (o groups)
    int ty = threadIdx.x >> 3;  // 0..7  (t groups)

    float acc[4][4] = {};

    for (int k0 = 0; k0 < NG; k0 += BK) {
        // load qA tile: consecutive threads read consecutive k (coalesced)
        for (int i = threadIdx.x; i < BK * BM; i += 64) {
            int mm = i / BK;
            int kk = i % BK;
            int t  = bm + mm;
            sA[kk][mm] = (t < NSTEP) ? g_qA[(size_t)t * NG + k0 + kk] : 0.0f;
        }
        // load idx tile: consecutive threads read consecutive n (coalesced)
        for (int i = threadIdx.x; i < BK * BN; i += 64) {
            int kk = i / BN;
            int nn = i % BN;
            int o  = bn + nn;
            sB[kk][nn] = (o < NOUT) ? idxm[(size_t)(k0 + kk) * NOUT + o] : 0.0f;
        }
        __syncthreads();

        #pragma unroll 8
        for (int k = 0; k < BK; k++) {
            float a[4], b[4];
            #pragma unroll
            for (int i = 0; i < 4; i++) a[i] = sA[k][ty * 4 + i];
            #pragma unroll
            for (int j = 0; j < 4; j++) b[j] = sB[k][tx * 4 + j];
            #pragma unroll
            for (int i = 0; i < 4; i++)
                #pragma unroll
                for (int j = 0; j < 4; j++)
                    acc[i][j] = fmaf(a[i], b[j], acc[i][j]);
        }
        __syncthreads();
    }

    #pragma unroll
    for (int i = 0; i < 4; i++) {
        int t = bm + ty * 4 + i;
        if (t >= NSTEP) continue;
        #pragma unroll
        for (int j = 0; j < 4; j++) {
            int o = bn + tx * 4 + j;
            if (o < NOUT) out[(size_t)t * NOUT + o] = acc[i][j];
        }
    }
}

// ---------------------------------------------------------------------------
extern "C" void kernel_launch(void* const* d_in, const int* in_sizes, int n_in,
                              void* d_out, int out_size) {
    const float* x      = (const float*)d_in[0];  // (730,2000,3)
    const float* params = (const float*)d_in[1];  // (730,2000,3,16)
    const float* wl     = (const float*)d_in[2];  // (2000,13,16)
    const float* Ai     = (const float*)d_in[3];  // (2000,)
    const float* Acb    = (const float*)d_in[4];  // (2000,)
    const float* idxm   = (const float*)d_in[5];  // (2000,500)
    float* out = (float*)d_out;                   // (730,500,1)

    hbv_scan_kernel<<<(NG * MU + 127) / 128, 128>>>(x, params, wl, Ai, Acb);

    dim3 grid((NOUT + BN - 1) / BN, (NSTEP + BM - 1) / BM);
    agg_gemm_kernel<<<grid, 64>>>(idxm, out);
}

// round 2
// speedup vs baseline: 3.2444x; 3.2444x over previous
#include <cuda_runtime.h>
#include <cuda_bf16.h>

#define NSTEP 730
#define NG    2000
#define MU    16
#define NOUT  500
#define PRECS 1e-5f

// Scratch: qA[t][g] = mean_mu(Q0+Q1+Q2) * Ai[g]
__device__ float g_qA[NSTEP * NG];

// ---------------------------------------------------------------------------
// Kernel 1: HBV scan. One thread per (grid, mu) lane. 32,000 threads.
// Depth-4 software pipeline: batch-issue 24 loads for steps t+4..t+7, then
// compute 4 steps — hides ~600cyc DRAM latency behind ~600cyc of compute.
// ---------------------------------------------------------------------------
__global__ __launch_bounds__(128)
void hbv_scan_kernel(const float* __restrict__ x,          // (730, 2000, 3)
                     const float* __restrict__ params,     // (730, 2000, 3, 16)
                     const float* __restrict__ wl,         // (2000, 13, 16)
                     const float* __restrict__ Ai,         // (2000,)
                     const float* __restrict__ Acb)        // (2000,)
{
    int tid = blockIdx.x * blockDim.x + threadIdx.x;
    if (tid >= NG * MU) return;
    int g = tid >> 4;
    int m = tid & 15;

    // ---- per-(g,m) waterloss parameters, scaled by SCA2 ----
    const float* w = wl + (size_t)g * 13 * MU + m;
    float parFC    = 50.0f   + w[0  * MU] * (1000.0f - 50.0f);
    float parK1    = 0.01f   + w[1  * MU] * (0.5f   - 0.01f);
    float parK2    = 0.001f  + w[2  * MU] * (0.2f   - 0.001f);
    float parLP    = 0.2f    + w[3  * MU] * (1.0f   - 0.2f);
    float parPERC  =           w[4  * MU] * 10.0f;
    float parUZL   =           w[5  * MU] * 100.0f;
    float parTT    = -2.5f   + w[6  * MU] * 5.0f;
    float parCFMAX = 0.5f    + w[7  * MU] * (10.0f  - 0.5f);
    float parCFR   =           w[8  * MU] * 0.1f;
    float parCWH   =           w[9  * MU] * 0.2f;
    float parC     =           w[10 * MU] * 1.0f;
    float parTR    =           w[11 * MU] * 20.0f;
    float parAc    =           w[12 * MU] * 2500.0f;

    float Ac  = Acb[g];
    float Aig = Ai[g] * 0.0625f;

    // regional_flow (computed once)
    float rf;
    {
        float c1 = fminf(fmaxf((Ac - parAc) * (1.0f / 1000.0f), -1.0f), 1.0f);
        float ea = fminf(fmaxf(-(Ac - 2500.0f) * (1.0f / 50.0f), -10.0f), 0.0f);
        float e  = expf(ea);
        rf = (Ac < 2500.0f) ? (c1 * parTR) : (e * parTR);
    }

    float invFC   = 1.0f / parFC;
    float invLPFC = 1.0f / (parLP * parFC);
    float CFRCF   = parCFR * parCFMAX;

    float SNOWPACK = 0.001f, MELTWATER = 0.001f, SM = 0.001f, SUZ = 0.001f, SLZ = 0.001f;

    const size_t SP = (size_t)NG * 3 * MU;  // params stride per t
    const size_t SX = (size_t)NG * 3;       // x stride per t
    const float* pb = params + (size_t)g * 3 * MU + m;
    const float* xb = x + (size_t)g * 3;

    float cB[4], cK[4], cBE[4], cP[4], cT[4], cE[4];
    float nB[4], nK[4], nBE[4], nP[4], nT[4], nE[4];

    #pragma unroll
    for (int u = 0; u < 4; u++) {
        const float* p = pb + (size_t)u * SP;
        const float* q = xb + (size_t)u * SX;
        cB[u]  = p[0];
        cK[u]  = p[MU];
        cBE[u] = p[2 * MU];
        cP[u]  = q[0];
        cT[u]  = q[1];
        cE[u]  = q[2];
    }

    float* qrow = g_qA + g;

    for (int tb = 0; tb < NSTEP; tb += 4) {
        // ---- batch-prefetch steps tb+4 .. tb+7 ----
        #pragma unroll
        for (int u = 0; u < 4; u++) {
            int tl = tb + 4 + u;
            bool v = tl < NSTEP;
            const float* p = pb + (size_t)tl * SP;
            const float* q = xb + (size_t)tl * SX;
            nB[u]  = v ? p[0]      : 0.0f;
            nK[u]  = v ? p[MU]     : 0.0f;
            nBE[u] = v ? p[2 * MU] : 0.0f;
            nP[u]  = v ? q[0]      : 0.0f;
            nT[u]  = v ? q[1]      : 0.0f;
            nE[u]  = v ? q[2]      : 0.0f;
        }

        // ---- compute 4 steps ----
        #pragma unroll
        for (int u = 0; u < 4; u++) {
            int t = tb + u;
            if (t >= NSTEP) break;

            float parBETA   = 1.0f  + cB[u]  * 5.0f;
            float parK0     = 0.05f + cK[u]  * 0.85f;
            float parBETAET = 0.3f  + cBE[u] * 4.7f;
            float Pt = cP[u], Tt = cT[u], Et = cE[u];

            float RAIN = (Tt >= parTT) ? Pt : 0.0f;
            float SNOW = Pt - RAIN;
            SNOWPACK += SNOW;
            float melt = fminf(fmaxf(parCFMAX * (Tt - parTT), 0.0f), SNOWPACK);
            MELTWATER += melt;
            SNOWPACK  -= melt;
            float refr = fminf(fmaxf(CFRCF * (parTT - Tt), 0.0f), MELTWATER);
            SNOWPACK  += refr;
            MELTWATER -= refr;
            float tosoil = fmaxf(MELTWATER - parCWH * SNOWPACK, 0.0f);
            MELTWATER -= tosoil;

            float sw = fminf(fmaxf(__powf(SM * invFC, parBETA), 0.0f), 1.0f);
            float recharge = (RAIN + tosoil) * sw;
            SM += RAIN + tosoil - recharge;
            float excess = fmaxf(SM - parFC, 0.0f);
            SM -= excess;

            float ef = fminf(fmaxf(__powf(SM * invLPFC, parBETAET), 0.0f), 1.0f);
            float ETact = fminf(SM, Et * ef);
            SM = fmaxf(SM - ETact, PRECS);

            float cap = fminf(SLZ, parC * SLZ * (1.0f - fminf(SM * invFC, 1.0f)));
            SM  = fmaxf(SM + cap, PRECS);
            SLZ = fmaxf(SLZ - cap, PRECS);

            SUZ += recharge + excess;
            float PERC = fminf(SUZ, parPERC);
            SUZ -= PERC;
            float Q0 = parK0 * fmaxf(SUZ - parUZL, 0.0f);
            SUZ -= Q0;
            float Q1 = parK1 * SUZ;
            SUZ -= Q1;
            SLZ += PERC;
            SLZ  = fmaxf(SLZ + rf, 0.0f);
            float Q2 = parK2 * SLZ;
            SLZ -= Q2;

            float q = Q0 + Q1 + Q2;
            q += __shfl_xor_sync(0xffffffffu, q, 8);
            q += __shfl_xor_sync(0xffffffffu, q, 4);
            q += __shfl_xor_sync(0xffffffffu, q, 2);
            q += __shfl_xor_sync(0xffffffffu, q, 1);
            if (m == 0) qrow[(size_t)t * NG] = q * Aig;
        }

        #pragma unroll
        for (int u = 0; u < 4; u++) {
            cB[u] = nB[u]; cK[u] = nK[u]; cBE[u] = nBE[u];
            cP[u] = nP[u]; cT[u] = nT[u]; cE[u]  = nE[u];
        }
    }
}

// ---------------------------------------------------------------------------
// Kernel 2b: zero output (out is poisoned to 0xAA; GEMM uses atomicAdd)
// ---------------------------------------------------------------------------
__global__ void zero_out_kernel(float* __restrict__ out, int n) {
    int i = blockIdx.x * blockDim.x + threadIdx.x;
    if (i < n) out[i] = 0.0f;
}

// ---------------------------------------------------------------------------
// Kernel 2: out[t][o] += sum_{g in chunk} qA[t][g] * idx[g][o]
// SGEMM M=730 (t), N=500 (o), K=2000 (g). BM=64, BN=64, BK=32, 256 threads,
// split-K=3 (288 blocks -> ~2/SM, all SMs busy). Conflict-free tiles.
// ---------------------------------------------------------------------------
#define BM 64
#define BN 64
#define BK 32
#define SPLITK 3
#define KCHUNK 672   // 672*3 = 2016 >= 2000 (tail zero-filled)

__global__ __launch_bounds__(256)
void agg_gemm_kernel(const float* __restrict__ idxm,  // (2000, 500)
                     float* __restrict__ out)         // (730, 500)
{
    __shared__ float sA[BM][BK];       // m-major: sA[m][k]
    __shared__ float sB[BK][BN];       // k-major: sB[k][n]

    int bm = blockIdx.y * BM;
    int bn = blockIdx.x * BN;
    int kstart = blockIdx.z * KCHUNK;
    int kend   = min(kstart + KCHUNK, NG);

    int tid = threadIdx.x;
    int tx = tid & 15;   // 0..15 (n groups of 4)
    int ty = tid >> 4;   // 0..15 (m groups of 4)

    float acc[4][4] = {};

    for (int k0 = kstart; k0 < kend; k0 += BK) {
        // load A tile: sA[mm][kk], consecutive threads -> consecutive kk (coalesced, conflict-free)
        #pragma unroll
        for (int i = tid; i < BM * BK; i += 256) {
            int mm = i >> 5;          // /BK
            int kk = i & 31;          // %BK
            int t = bm + mm;
            int k = k0 + kk;
            sA[mm][kk] = (t < NSTEP && k < kend) ? g_qA[(size_t)t * NG + k] : 0.0f;
        }
        // load B tile: sB[kk][nn], consecutive threads -> consecutive nn (coalesced, conflict-free)
        #pragma unroll
        for (int i = tid; i < BK * BN; i += 256) {
            int kk = i >> 6;          // /BN
            int nn = i & 63;          // %BN
            int k = k0 + kk;
            int o = bn + nn;
            sB[kk][nn] = (k < kend && o < NOUT) ? idxm[(size_t)k * NOUT + o] : 0.0f;
        }
        __syncthreads();

        #pragma unroll 4
        for (int k = 0; k < BK; k++) {
            float a0 = sA[ty * 4 + 0][k];
            float a1 = sA[ty * 4 + 1][k];
            float a2 = sA[ty * 4 + 2][k];
            float a3 = sA[ty * 4 + 3][k];
            float4 b = *reinterpret_cast<const float4*>(&sB[k][tx * 4]);
            float bb[4] = {b.x, b.y, b.z, b.w};
            float aa[4] = {a0, a1, a2, a3};
            #pragma unroll
            for (int i = 0; i < 4; i++)
                #pragma unroll
                for (int j = 0; j < 4; j++)
                    acc[i][j] = fmaf(aa[i], bb[j], acc[i][j]);
        }
        __syncthreads();
    }

    #pragma unroll
    for (int i = 0; i < 4; i++) {
        int t = bm + ty * 4 + i;
        if (t >= NSTEP) continue;
        #pragma unroll
        for (int j = 0; j < 4; j++) {
            int o = bn + tx * 4 + j;
            if (o < NOUT) atomicAdd(&out[(size_t)t * NOUT + o], acc[i][j]);
        }
    }
}

// ---------------------------------------------------------------------------
extern "C" void kernel_launch(void* const* d_in, const int* in_sizes, int n_in,
                              void* d_out, int out_size) {
    const float* x      = (const float*)d_in[0];  // (730,2000,3)
    const float* params = (const float*)d_in[1];  // (730,2000,3,16)
    const float* wl     = (const float*)d_in[2];  // (2000,13,16)
    const float* Ai     = (const float*)d_in[3];  // (2000,)
    const float* Acb    = (const float*)d_in[4];  // (2000,)
    const float* idxm   = (const float*)d_in[5];  // (2000,500)
    float* out = (float*)d_out;                   // (730,500,1)

    hbv_scan_kernel<<<(NG * MU + 127) / 128, 128>>>(x, params, wl, Ai, Acb);

    int n = NSTEP * NOUT;
    zero_out_kernel<<<(n + 511) / 512, 512>>>(out, n);

    dim3 grid((NOUT + BN - 1) / BN, (NSTEP + BM - 1) / BM, SPLITK);
    agg_gemm_kernel<<<grid, 256>>>(idxm, out);
}